// round 12
// baseline (speedup 1.0000x reference)
#include <cuda_runtime.h>
#include <cstdint>

#define B_ 4
#define S_ 2048
#define E_ 1024
#define H_ 128
#define M_ (B_*S_)

#define SCALE_ 11.31370849898476f   // sqrt(128)

#define NSPLIT 4
#define KT 32
#define QTB 64           // q rows per block
#define NQT (S_/QTB)     // 32 q-tiles per batch

// Scratch (device globals: no allocation allowed)
__device__ float g_q[M_*H_];
__device__ float g_k[M_*H_];
__device__ float g_v[M_*H_];
__device__ float g_opart[(size_t)NSPLIT*M_*H_];
__device__ float g_mpart[NSPLIT*M_];
__device__ float g_lpart[NSPLIT*M_];

// ---------------------------------------------------------------------------
// tf32 helpers
// ---------------------------------------------------------------------------
__device__ __forceinline__ unsigned f2tf(float x) {
    unsigned r;
    asm("cvt.rna.tf32.f32 %0, %1;" : "=r"(r) : "f"(x));
    return r;
}
__device__ __forceinline__ void split_tf(float x, unsigned& hi, unsigned& lo) {
    hi = f2tf(x);
    lo = f2tf(x - __uint_as_float(hi));
}

#define MMA_TF32(d, a, b) \
    asm volatile("mma.sync.aligned.m16n8k8.row.col.f32.tf32.tf32.f32 " \
        "{%0,%1,%2,%3}, {%4,%5,%6,%7}, {%8,%9}, {%0,%1,%2,%3};" \
        : "+f"((d)[0]), "+f"((d)[1]), "+f"((d)[2]), "+f"((d)[3]) \
        : "r"((a)[0]), "r"((a)[1]), "r"((a)[2]), "r"((a)[3]), \
          "r"((b)[0]), "r"((b)[1]))

#define CP_ASYNC16(dst, src) \
    asm volatile("cp.async.cg.shared.global [%0], [%1], 16;\n" \
        :: "r"(dst), "l"(src))
#define CP_COMMIT() asm volatile("cp.async.commit_group;\n" ::: "memory")
#define CP_WAIT(n)  asm volatile("cp.async.wait_group %0;\n" :: "n"(n) : "memory")

// ---------------------------------------------------------------------------
// Projection GEMM via tf32x3 mma: out[m][h] = sum_e x[m][e]*W[h][e]
// BM=64, BN=128(=H), BK=32, double-buffered cp.async pipeline.
// 128 threads = 4 warps (2m x 2n), warp tile 32x64.
// BK=32 halves barrier count vs BK=16; smem = 2*(64+128)*32*4 = 48KB static.
// Swizzle: float4 slot c4 (0..7) of row r stored at c4 ^ (r&7); fragment
// rows all have r&7 == g, so reads fold to per-thread constants.
// ---------------------------------------------------------------------------
__global__ __launch_bounds__(128, 4) void proj_kernel(
    const float* __restrict__ x,
    const float* __restrict__ Wq,
    const float* __restrict__ Wk,
    const float* __restrict__ Wv)
{
    const float* W;
    float* out;
    float oscale;
    if (blockIdx.y == 0)      { W = Wq; out = g_q; oscale = SCALE_; }
    else if (blockIdx.y == 1) { W = Wk; out = g_k; oscale = 1.0f; }
    else                      { W = Wv; out = g_v; oscale = 1.0f; }

    __shared__ float Xs[2][64 * 32];    // 8KB each
    __shared__ float Ws[2][128 * 32];   // 16KB each

    const int tid  = threadIdx.x;
    const int w    = tid >> 5;
    const int lane = tid & 31;
    const int g    = lane >> 2;
    const int tig  = lane & 3;

    const int m0 = blockIdx.x * 64;
    const int mw = (w >> 1) * 32;    // warp m-base (0 or 32)
    const int nw = (w & 1) * 64;     // warp n-base (0 or 64)

    // per-thread load slots: 4 f4 of X, 8 f4 of W  (rows of 8 f4 slots)
    int soffx[4], soffw[8];
    const float* xsrc[4];
    const float* wsrc[8];
#pragma unroll
    for (int i = 0; i < 4; i++) {
        int f4 = tid + 128 * i;          // 0..511
        int row = f4 >> 3, c4 = f4 & 7;
        soffx[i] = row * 32 + ((c4 ^ (row & 7)) << 2);
        xsrc[i]  = &x[(size_t)(m0 + row) * E_ + c4 * 4];
    }
#pragma unroll
    for (int i = 0; i < 8; i++) {
        int f4 = tid + 128 * i;          // 0..1023
        int row = f4 >> 3, c4 = f4 & 7;
        soffw[i] = row * 32 + ((c4 ^ (row & 7)) << 2);
        wsrc[i]  = &W[(size_t)row * E_ + c4 * 4];
    }

    unsigned xs_u32[2], ws_u32[2];
#pragma unroll
    for (int bb = 0; bb < 2; bb++) {
        xs_u32[bb] = (unsigned)__cvta_generic_to_shared(&Xs[bb][0]);
        ws_u32[bb] = (unsigned)__cvta_generic_to_shared(&Ws[bb][0]);
    }

    float acc[2][8][4];
#pragma unroll
    for (int i = 0; i < 2; i++)
#pragma unroll
        for (int j = 0; j < 8; j++)
#pragma unroll
            for (int c = 0; c < 4; c++) acc[i][j][c] = 0.0f;

    const float* xfr[2];
    xfr[0] = &Xs[0][(mw + g) * 32 + tig];
    xfr[1] = &Xs[1][(mw + g) * 32 + tig];
    const float* wfr[2];
    wfr[0] = &Ws[0][(nw + g) * 32 + tig];
    wfr[1] = &Ws[1][(nw + g) * 32 + tig];

    // prologue: load tile 0 into buffer 0
#pragma unroll
    for (int i = 0; i < 4; i++) CP_ASYNC16(xs_u32[0] + soffx[i] * 4, xsrc[i]);
#pragma unroll
    for (int i = 0; i < 8; i++) CP_ASYNC16(ws_u32[0] + soffw[i] * 4, wsrc[i]);
    CP_COMMIT();

    for (int t = 0; t < E_ / 32; t++) {
        const int buf = t & 1;
        if (t + 1 < E_ / 32) {
            const int nb = (t + 1) & 1;
            const int ko = (t + 1) * 32;
#pragma unroll
            for (int i = 0; i < 4; i++)
                CP_ASYNC16(xs_u32[nb] + soffx[i] * 4, xsrc[i] + ko);
#pragma unroll
            for (int i = 0; i < 8; i++)
                CP_ASYNC16(ws_u32[nb] + soffw[i] * 4, wsrc[i] + ko);
            CP_COMMIT();
            CP_WAIT(1);
        } else {
            CP_WAIT(0);
        }
        __syncthreads();

#pragma unroll
        for (int kk = 0; kk < 4; kk++) {
            const int s0 = ((2 * kk)     ^ g) << 2;   // k = 8kk+tig
            const int s1 = ((2 * kk + 1) ^ g) << 2;   // k = 8kk+4+tig

            unsigned aH[2][4], aL[2][4];
#pragma unroll
            for (int i = 0; i < 2; i++) {
                const float* xr = xfr[buf] + 16 * 32 * i;   // rows mw+16i+g
                split_tf(xr[s0],           aH[i][0], aL[i][0]);
                split_tf(xr[8 * 32 + s0],  aH[i][1], aL[i][1]);
                split_tf(xr[s1],           aH[i][2], aL[i][2]);
                split_tf(xr[8 * 32 + s1],  aH[i][3], aL[i][3]);
            }
#pragma unroll
            for (int j = 0; j < 8; j++) {
                const float* wr = wfr[buf] + 8 * 32 * j;    // rows nw+8j+g
                unsigned bH[2], bL[2];
                split_tf(wr[s0], bH[0], bL[0]);
                split_tf(wr[s1], bH[1], bL[1]);
#pragma unroll
                for (int i = 0; i < 2; i++) {
                    MMA_TF32(acc[i][j], aH[i], bH);
                    MMA_TF32(acc[i][j], aH[i], bL);
                    MMA_TF32(acc[i][j], aL[i], bH);
                }
            }
        }
        __syncthreads();
    }

    // --- epilogue: C rows m0+mw+16i+{g, g+8}, cols nw+8j+2tig(+1) ---
#pragma unroll
    for (int i = 0; i < 2; i++) {
        const size_t r0 = (size_t)(m0 + mw + 16 * i + g);
#pragma unroll
        for (int j = 0; j < 8; j++) {
            const int col = nw + 8 * j + 2 * tig;
            *(float2*)&out[r0 * H_ + col] =
                make_float2(acc[i][j][0] * oscale, acc[i][j][1] * oscale);
            *(float2*)&out[(r0 + 8) * H_ + col] =
                make_float2(acc[i][j][2] * oscale, acc[i][j][3] * oscale);
        }
    }
}

// ---------------------------------------------------------------------------
// Flash attention: tf32x3 mma.sync. 128 threads (4 warps), QTB=64, KT=32,
// NSPLIT=4 k-split. Static smem = 49152 B exactly.
// NEW: K(t+1) prefetched into registers during AV; V(t) prefetched during
// softmax — global-load latency hidden behind compute. Arithmetic unchanged.
// ---------------------------------------------------------------------------
__global__ __launch_bounds__(128, 4) void attn_kernel()
{
    __shared__ float Qs[QTB * 128];   // 32KB
    __shared__ float KVs[KT * 128];   // 16KB (K phase, then V phase)

    const int tid  = threadIdx.x;
    const int w    = tid >> 5;
    const int lane = tid & 31;
    const int g    = lane >> 2;
    const int tig  = lane & 3;

    const int bx   = blockIdx.x;
    const int wave = bx / 148;
    const int pos  = bx - wave * 148;
    int r;
    if      (wave == 1) r = 295 - pos;
    else if (wave == 3) r = 511 - pos;
    else                r = bx;

    const int qt    = (NQT - 1) - (r >> 4);
    const int sub   = r & 15;
    const int b     = sub & 3;
    const int split = sub >> 2;

    const int nkt = 2 * (qt + 1);
    const int ck  = (nkt + NSPLIT - 1) / NSPLIT;
    const int ks0 = split * ck;
    const int ks1 = min(ks0 + ck, nkt);
    if (ks0 >= ks1) return;

    const int    qb   = qt * QTB;
    const size_t base = (size_t)b * S_;

    // per-thread KV load slot geometry (8 float4, rows 0..31)
    int kvrow[8], kvc4[8], kvsoff[8];
#pragma unroll
    for (int i = 0; i < 8; i++) {
        int f4 = tid + 128 * i;
        kvrow[i]  = f4 >> 5;
        kvc4[i]   = f4 & 31;
        kvsoff[i] = kvrow[i] * 128 + ((kvc4[i] ^ (kvrow[i] & 7)) << 2);
    }

#pragma unroll
    for (int i = 0; i < 16; i++) {
        int f4 = tid + 128 * i;
        int row = f4 >> 5, c4 = f4 & 31;
        *(float4*)&Qs[row * 128 + ((c4 ^ (row & 7)) << 2)] =
            *(const float4*)&g_q[(base + qb + row) * H_ + c4 * 4];
    }

    float acc[16][4];
#pragma unroll
    for (int nt = 0; nt < 16; nt++)
#pragma unroll
        for (int j = 0; j < 4; j++) acc[nt][j] = 0.0f;

    float mA = -1e30f, mB = -1e30f, lA = 0.0f, lB = 0.0f;
    const int rA   = 16 * w + g;
    const int rowA = qb + rA;
    const int rowB = rowA + 8;

    const float* qrowA = &Qs[rA * 128 + tig];
    const float* qrowB = qrowA + 8 * 128;

    // prefetch K tile ks0 into registers
    float4 kreg[8];
    {
        const int kb0 = ks0 * KT;
#pragma unroll
        for (int i = 0; i < 8; i++)
            kreg[i] = *(const float4*)&g_k[(base + kb0 + kvrow[i]) * H_ + kvc4[i] * 4];
    }

    for (int kt = ks0; kt < ks1; kt++) {
        const int kb = kt * KT;

        __syncthreads();   // prior AV reads / Q-load done
        // --- store prefetched K tile ---
#pragma unroll
        for (int i = 0; i < 8; i++)
            *(float4*)&KVs[kvsoff[i]] = kreg[i];
        __syncthreads();

        float s[4][4];
#pragma unroll
        for (int nt = 0; nt < 4; nt++)
#pragma unroll
            for (int j = 0; j < 4; j++) s[nt][j] = 0.0f;

#pragma unroll
        for (int ks = 0; ks < 16; ks++) {
            const int c0 = ((2 * ks)     ^ g) << 2;
            const int c1 = ((2 * ks + 1) ^ g) << 2;
            unsigned aH[4], aL[4];
            split_tf(qrowA[c0], aH[0], aL[0]);
            split_tf(qrowB[c0], aH[1], aL[1]);
            split_tf(qrowA[c1], aH[2], aL[2]);
            split_tf(qrowB[c1], aH[3], aL[3]);
#pragma unroll
            for (int nt = 0; nt < 4; nt++) {
                const float* kr = &KVs[(8 * nt + g) * 128 + tig];
                unsigned bH[2], bL[2];
                split_tf(kr[c0], bH[0], bL[0]);
                split_tf(kr[c1], bH[1], bL[1]);
                MMA_TF32(s[nt], aH, bH);
                MMA_TF32(s[nt], aH, bL);
                MMA_TF32(s[nt], aL, bH);
            }
        }

        // --- prefetch V tile (LDG latency hidden under softmax) ---
        float4 vreg[8];
#pragma unroll
        for (int i = 0; i < 8; i++)
            vreg[i] = *(const float4*)&g_v[(base + kb + kvrow[i]) * H_ + kvc4[i] * 4];

        // --- causal mask ---
#pragma unroll
        for (int nt = 0; nt < 4; nt++) {
            int c0 = kb + 8 * nt + 2 * tig;
            int c1 = c0 + 1;
            if (c0 > rowA) s[nt][0] = -1e30f;
            if (c1 > rowA) s[nt][1] = -1e30f;
            if (c0 > rowB) s[nt][2] = -1e30f;
            if (c1 > rowB) s[nt][3] = -1e30f;
        }

        // --- online softmax ---
        float mxA = -1e30f, mxB = -1e30f;
#pragma unroll
        for (int nt = 0; nt < 4; nt++) {
            mxA = fmaxf(mxA, fmaxf(s[nt][0], s[nt][1]));
            mxB = fmaxf(mxB, fmaxf(s[nt][2], s[nt][3]));
        }
        mxA = fmaxf(mxA, __shfl_xor_sync(0xffffffffu, mxA, 1));
        mxA = fmaxf(mxA, __shfl_xor_sync(0xffffffffu, mxA, 2));
        mxB = fmaxf(mxB, __shfl_xor_sync(0xffffffffu, mxB, 1));
        mxB = fmaxf(mxB, __shfl_xor_sync(0xffffffffu, mxB, 2));

        float mAn = fmaxf(mA, mxA), mBn = fmaxf(mB, mxB);
        float cA = __expf(mA - mAn), cB = __expf(mB - mBn);
        float sumA = 0.0f, sumB = 0.0f;
#pragma unroll
        for (int nt = 0; nt < 4; nt++) {
            s[nt][0] = __expf(s[nt][0] - mAn);
            s[nt][1] = __expf(s[nt][1] - mAn);
            s[nt][2] = __expf(s[nt][2] - mBn);
            s[nt][3] = __expf(s[nt][3] - mBn);
            sumA += s[nt][0] + s[nt][1];
            sumB += s[nt][2] + s[nt][3];
        }
        sumA += __shfl_xor_sync(0xffffffffu, sumA, 1);
        sumA += __shfl_xor_sync(0xffffffffu, sumA, 2);
        sumB += __shfl_xor_sync(0xffffffffu, sumB, 1);
        sumB += __shfl_xor_sync(0xffffffffu, sumB, 2);
        lA = lA * cA + sumA;
        lB = lB * cB + sumB;
        mA = mAn; mB = mBn;
#pragma unroll
        for (int nt = 0; nt < 16; nt++) {
            acc[nt][0] *= cA; acc[nt][1] *= cA;
            acc[nt][2] *= cB; acc[nt][3] *= cB;
        }

        __syncthreads();   // QK reads of KVs done
        // --- store prefetched V tile ---
#pragma unroll
        for (int i = 0; i < 8; i++)
            *(float4*)&KVs[kvsoff[i]] = vreg[i];
        __syncthreads();

        // --- prefetch K tile kt+1 (LDG latency hidden under AV) ---
        if (kt + 1 < ks1) {
            const int kbn = (kt + 1) * KT;
#pragma unroll
            for (int i = 0; i < 8; i++)
                kreg[i] = *(const float4*)&g_k[(base + kbn + kvrow[i]) * H_ + kvc4[i] * 4];
        }

        // --- AV ---
        const int srcE = (lane & ~3) | (tig >> 1);
        const int srcO = srcE + 2;
        const int gh   = g >> 2;
        const int gl   = g & 3;
#pragma unroll
        for (int ka = 0; ka < 4; ka++) {
            float e, o, a0f, a1f, a2f, a3f;
            e = __shfl_sync(0xffffffffu, s[ka][0], srcE);
            o = __shfl_sync(0xffffffffu, s[ka][1], srcE);
            a0f = (tig & 1) ? o : e;
            e = __shfl_sync(0xffffffffu, s[ka][0], srcO);
            o = __shfl_sync(0xffffffffu, s[ka][1], srcO);
            a2f = (tig & 1) ? o : e;
            e = __shfl_sync(0xffffffffu, s[ka][2], srcE);
            o = __shfl_sync(0xffffffffu, s[ka][3], srcE);
            a1f = (tig & 1) ? o : e;
            e = __shfl_sync(0xffffffffu, s[ka][2], srcO);
            o = __shfl_sync(0xffffffffu, s[ka][3], srcO);
            a3f = (tig & 1) ? o : e;

            unsigned aH[4], aL[4];
            split_tf(a0f, aH[0], aL[0]);
            split_tf(a1f, aH[1], aL[1]);
            split_tf(a2f, aH[2], aL[2]);
            split_tf(a3f, aH[3], aL[3]);

            const float* v0 = &KVs[(8 * ka + tig) * 128 + gl];
            const float* v1 = &KVs[(8 * ka + tig + 4) * 128 + gl];
#pragma unroll
            for (int nt = 0; nt < 16; nt++) {
                const int o0 = ((2 * nt + gh) ^ tig) << 2;
                const int o1 = o0 ^ 16;
                unsigned bH[2], bL[2];
                split_tf(v0[o0], bH[0], bL[0]);
                split_tf(v1[o1], bH[1], bL[1]);
                MMA_TF32(acc[nt], aH, bH);
                MMA_TF32(acc[nt], aH, bL);
                MMA_TF32(acc[nt], aL, bH);
            }
        }
    }

    const size_t growA = (size_t)split * M_ + base + rowA;
    const size_t growB = growA + 8;
#pragma unroll
    for (int nt = 0; nt < 16; nt++) {
        *(float2*)&g_opart[growA * H_ + 8 * nt + 2 * tig] =
            make_float2(acc[nt][0], acc[nt][1]);
        *(float2*)&g_opart[growB * H_ + 8 * nt + 2 * tig] =
            make_float2(acc[nt][2], acc[nt][3]);
    }
    if (tig == 0) {
        g_mpart[growA] = mA; g_lpart[growA] = lA;
        g_mpart[growB] = mB; g_lpart[growB] = lB;
    }
}

// ---------------------------------------------------------------------------
// Combine kernel: merge NSPLIT partials per row.
// ---------------------------------------------------------------------------
__global__ __launch_bounds__(256) void combine_kernel(float* __restrict__ out)
{
    const int t   = blockIdx.x * 256 + threadIdx.x;
    const int row = t >> 5;
    const int h   = (t & 31) * 4;

    const int qt  = (row & (S_ - 1)) >> 6;            // QTB=64
    const int nkt = 2 * (qt + 1);
    const int ck  = (nkt + NSPLIT - 1) / NSPLIT;

    float ms[NSPLIT];
    float M = -1e30f;
#pragma unroll
    for (int sp = 0; sp < NSPLIT; sp++) {
        bool valid = (sp * ck < nkt);
        ms[sp] = valid ? g_mpart[sp * M_ + row] : -1e30f;
        M = fmaxf(M, ms[sp]);
    }

    float L = 0.0f;
    float4 o = make_float4(0.f, 0.f, 0.f, 0.f);
#pragma unroll
    for (int sp = 0; sp < NSPLIT; sp++) {
        if (sp * ck < nkt) {
            float e = __expf(ms[sp] - M);
            L += e * g_lpart[sp * M_ + row];
            float4 v = *(const float4*)&g_opart[((size_t)sp * M_ + row) * H_ + h];
            o.x += e * v.x; o.y += e * v.y; o.z += e * v.z; o.w += e * v.w;
        }
    }
    float inv = 1.0f / L;
    float4 rr = make_float4(o.x * inv, o.y * inv, o.z * inv, o.w * inv);
    *(float4*)&out[(size_t)row * H_ + h] = rr;
}

// ---------------------------------------------------------------------------
extern "C" void kernel_launch(void* const* d_in, const int* in_sizes, int n_in,
                              void* d_out, int out_size)
{
    const float* x  = (const float*)d_in[0];
    const float* Wq = (const float*)d_in[1];
    const float* Wk = (const float*)d_in[2];
    const float* Wv = (const float*)d_in[3];
    float* out = (float*)d_out;

    dim3 pg(M_ / 64, 3);
    proj_kernel<<<pg, 128>>>(x, Wq, Wk, Wv);
    attn_kernel<<<NSPLIT * B_ * NQT, 128>>>();
    combine_kernel<<<(M_ * H_ / 4) / 256, 256>>>(out);
}

// round 13
// speedup vs baseline: 1.4505x; 1.4505x over previous
#include <cuda_runtime.h>
#include <cuda_fp16.h>
#include <cstdint>

#define B_ 4
#define S_ 2048
#define E_ 1024
#define H_ 128
#define M_ (B_*S_)

#define SCALE_ 11.31370849898476f   // sqrt(128)

#define NSPLIT 4
#define KT 32
#define QTB 64           // q rows per block
#define NQT (S_/QTB)     // 32 q-tiles per batch

// Scratch (device globals: no allocation allowed)
__device__ float g_q[M_*H_];
__device__ float g_k[M_*H_];
__device__ float g_v[M_*H_];
__device__ float g_opart[(size_t)NSPLIT*M_*H_];
__device__ float g_mpart[NSPLIT*M_];
__device__ float g_lpart[NSPLIT*M_];

// ---------------------------------------------------------------------------
// tf32 helpers (proj)
// ---------------------------------------------------------------------------
__device__ __forceinline__ unsigned f2tf(float x) {
    unsigned r;
    asm("cvt.rna.tf32.f32 %0, %1;" : "=r"(r) : "f"(x));
    return r;
}
__device__ __forceinline__ void split_tf(float x, unsigned& hi, unsigned& lo) {
    hi = f2tf(x);
    lo = f2tf(x - __uint_as_float(hi));
}

#define MMA_TF32(d, a, b) \
    asm volatile("mma.sync.aligned.m16n8k8.row.col.f32.tf32.tf32.f32 " \
        "{%0,%1,%2,%3}, {%4,%5,%6,%7}, {%8,%9}, {%0,%1,%2,%3};" \
        : "+f"((d)[0]), "+f"((d)[1]), "+f"((d)[2]), "+f"((d)[3]) \
        : "r"((a)[0]), "r"((a)[1]), "r"((a)[2]), "r"((a)[3]), \
          "r"((b)[0]), "r"((b)[1]))

// fp16 helpers (attn)
__device__ __forceinline__ void split_h2(float2 v, unsigned& hi, unsigned& lo) {
    __half2 h = __floats2half2_rn(v.x, v.y);       // low half = v.x (k-even)
    float2 hf = __half22float2(h);
    __half2 l = __floats2half2_rn(v.x - hf.x, v.y - hf.y);
    hi = *reinterpret_cast<unsigned*>(&h);
    lo = *reinterpret_cast<unsigned*>(&l);
}

#define MMA_F16(d, a, b) \
    asm volatile("mma.sync.aligned.m16n8k16.row.col.f32.f16.f16.f32 " \
        "{%0,%1,%2,%3}, {%4,%5,%6,%7}, {%8,%9}, {%0,%1,%2,%3};" \
        : "+f"((d)[0]), "+f"((d)[1]), "+f"((d)[2]), "+f"((d)[3]) \
        : "r"((a)[0]), "r"((a)[1]), "r"((a)[2]), "r"((a)[3]), \
          "r"((b)[0]), "r"((b)[1]))

#define CP_ASYNC16(dst, src) \
    asm volatile("cp.async.cg.shared.global [%0], [%1], 16;\n" \
        :: "r"(dst), "l"(src))
#define CP_COMMIT() asm volatile("cp.async.commit_group;\n" ::: "memory")
#define CP_WAIT(n)  asm volatile("cp.async.wait_group %0;\n" :: "n"(n) : "memory")

// ---------------------------------------------------------------------------
// Projection GEMM via tf32x3 mma (R11 verified build, 137.8us):
// BM=64, BN=128, BK=16, cp.async double-buffer, 128 threads, warp tile 32x64.
// ---------------------------------------------------------------------------
__global__ __launch_bounds__(128, 4) void proj_kernel(
    const float* __restrict__ x,
    const float* __restrict__ Wq,
    const float* __restrict__ Wk,
    const float* __restrict__ Wv)
{
    const float* W;
    float* out;
    float oscale;
    if (blockIdx.y == 0)      { W = Wq; out = g_q; oscale = SCALE_; }
    else if (blockIdx.y == 1) { W = Wk; out = g_k; oscale = 1.0f; }
    else                      { W = Wv; out = g_v; oscale = 1.0f; }

    __shared__ float Xs[2][64 * 16];    // 4KB each
    __shared__ float Ws[2][128 * 16];   // 8KB each

    const int tid  = threadIdx.x;
    const int w    = tid >> 5;
    const int lane = tid & 31;
    const int g    = lane >> 2;
    const int tig  = lane & 3;

    const int m0 = blockIdx.x * 64;
    const int mw = (w >> 1) * 32;
    const int nw = (w & 1) * 64;

    const int rl  = tid >> 2, c4l = tid & 3;
    int soffx[2], soffw[4];
    const float* xsrc[2];
    const float* wsrc[4];
#pragma unroll
    for (int i = 0; i < 2; i++) {
        int row = rl + 32 * i;
        soffx[i] = row * 16 + ((c4l ^ ((row >> 1) & 3)) << 2);
        xsrc[i]  = &x[(size_t)(m0 + row) * E_ + c4l * 4];
    }
#pragma unroll
    for (int i = 0; i < 4; i++) {
        int row = rl + 32 * i;
        soffw[i] = row * 16 + ((c4l ^ ((row >> 1) & 3)) << 2);
        wsrc[i]  = &W[(size_t)row * E_ + c4l * 4];
    }

    unsigned xs_u32[2], ws_u32[2];
#pragma unroll
    for (int bb = 0; bb < 2; bb++) {
        xs_u32[bb] = (unsigned)__cvta_generic_to_shared(&Xs[bb][0]);
        ws_u32[bb] = (unsigned)__cvta_generic_to_shared(&Ws[bb][0]);
    }

    float acc[2][8][4];
#pragma unroll
    for (int i = 0; i < 2; i++)
#pragma unroll
        for (int j = 0; j < 8; j++)
#pragma unroll
            for (int c = 0; c < 4; c++) acc[i][j][c] = 0.0f;

    const int sw = (g >> 1) & 3;
    const int o0k0 = ((0 ^ sw) << 2);
    const int o1k0 = ((1 ^ sw) << 2);
    const int o0k1 = ((2 ^ sw) << 2);
    const int o1k1 = ((3 ^ sw) << 2);

    const float* xfr[2];
    xfr[0] = &Xs[0][(mw + g) * 16 + tig];
    xfr[1] = &Xs[1][(mw + g) * 16 + tig];
    const float* wfr[2];
    wfr[0] = &Ws[0][(nw + g) * 16 + tig];
    wfr[1] = &Ws[1][(nw + g) * 16 + tig];

#pragma unroll
    for (int i = 0; i < 2; i++) CP_ASYNC16(xs_u32[0] + soffx[i] * 4, xsrc[i]);
#pragma unroll
    for (int i = 0; i < 4; i++) CP_ASYNC16(ws_u32[0] + soffw[i] * 4, wsrc[i]);
    CP_COMMIT();

    for (int t = 0; t < E_ / 16; t++) {
        const int buf = t & 1;
        if (t + 1 < E_ / 16) {
            const int nb = (t + 1) & 1;
            const int ko = (t + 1) * 16;
#pragma unroll
            for (int i = 0; i < 2; i++)
                CP_ASYNC16(xs_u32[nb] + soffx[i] * 4, xsrc[i] + ko);
#pragma unroll
            for (int i = 0; i < 4; i++)
                CP_ASYNC16(ws_u32[nb] + soffw[i] * 4, wsrc[i] + ko);
            CP_COMMIT();
            CP_WAIT(1);
        } else {
            CP_WAIT(0);
        }
        __syncthreads();

#pragma unroll
        for (int kk = 0; kk < 2; kk++) {
            const int s0 = kk ? o0k1 : o0k0;
            const int s1 = kk ? o1k1 : o1k0;

            unsigned aH[2][4], aL[2][4];
#pragma unroll
            for (int i = 0; i < 2; i++) {
                const float* xr = xfr[buf] + 16 * 16 * i;
                split_tf(xr[s0],           aH[i][0], aL[i][0]);
                split_tf(xr[8 * 16 + s0],  aH[i][1], aL[i][1]);
                split_tf(xr[s1],           aH[i][2], aL[i][2]);
                split_tf(xr[8 * 16 + s1],  aH[i][3], aL[i][3]);
            }
#pragma unroll
            for (int j = 0; j < 8; j++) {
                const float* wr = wfr[buf] + 8 * 16 * j;
                unsigned bH[2], bL[2];
                split_tf(wr[s0], bH[0], bL[0]);
                split_tf(wr[s1], bH[1], bL[1]);
#pragma unroll
                for (int i = 0; i < 2; i++) {
                    MMA_TF32(acc[i][j], aH[i], bH);
                    MMA_TF32(acc[i][j], aH[i], bL);
                    MMA_TF32(acc[i][j], aL[i], bH);
                }
            }
        }
        __syncthreads();
    }

#pragma unroll
    for (int i = 0; i < 2; i++) {
        const size_t r0 = (size_t)(m0 + mw + 16 * i + g);
#pragma unroll
        for (int j = 0; j < 8; j++) {
            const int col = nw + 8 * j + 2 * tig;
            *(float2*)&out[r0 * H_ + col] =
                make_float2(acc[i][j][0] * oscale, acc[i][j][1] * oscale);
            *(float2*)&out[(r0 + 8) * H_ + col] =
                make_float2(acc[i][j][2] * oscale, acc[i][j][3] * oscale);
        }
    }
}

// ---------------------------------------------------------------------------
// Flash attention: fp16x3 split mma.m16n8k16. 128 threads (4 warps),
// QTB=64, KT=32, NSPLIT=4.
// Pre-split operands once into fp16x2 hi/lo smem planes:
//   QH/QL[64 rows][64 h-pairs]  (per block; swizzle: pair ^ 8*(row&7))
//   KH/KL[32 rows][64 h-pairs]  (per tile;  same swizzle)      [KVu buffer]
//   VH/VL[16 key-pairs][128 h]  (per tile;  swizzle: col ^ 8*(kp&3))
// QK/AV fragment loads are bare LDS.32; AV A-frag (P) is thread-local
// (m16n8k16 A k-pairs == C-frag column pairs) -> zero shuffles.
// Static smem = 16+16+16 = 48KB exactly.
// ---------------------------------------------------------------------------
__global__ __launch_bounds__(128, 4) void attn_kernel()
{
    __shared__ unsigned QHu[QTB * 64];   // 16KB
    __shared__ unsigned QLu[QTB * 64];   // 16KB
    __shared__ unsigned KVu[KT * 128];   // 16KB: K phase KH|KL (2048+2048),
                                         //        V phase VH|VL (2048+2048)
    const int tid  = threadIdx.x;
    const int w    = tid >> 5;
    const int lane = tid & 31;
    const int g    = lane >> 2;
    const int tig  = lane & 3;

    const int bx   = blockIdx.x;
    const int wave = bx / 148;
    const int pos  = bx - wave * 148;
    int r;
    if      (wave == 1) r = 295 - pos;
    else if (wave == 3) r = 511 - pos;
    else                r = bx;

    const int qt    = (NQT - 1) - (r >> 4);
    const int sub   = r & 15;
    const int b     = sub & 3;
    const int split = sub >> 2;

    const int nkt = 2 * (qt + 1);
    const int ck  = (nkt + NSPLIT - 1) / NSPLIT;
    const int ks0 = split * ck;
    const int ks1 = min(ks0 + ck, nkt);
    if (ks0 >= ks1) return;

    const int    qb   = qt * QTB;
    const size_t base = (size_t)b * S_;

    // --- load + split Q once per block (pre-scaled by sqrt(H)) ---
#pragma unroll
    for (int i = 0; i < 16; i++) {
        int f4 = tid + 128 * i;            // 0..2047
        int row = f4 >> 5, c4 = f4 & 31;
        float4 v = *(const float4*)&g_q[(base + qb + row) * H_ + c4 * 4];
        unsigned h0, l0, h1, l1;
        split_h2(make_float2(v.x, v.y), h0, l0);
        split_h2(make_float2(v.z, v.w), h1, l1);
        int off = row * 64 + ((2 * c4) ^ ((row & 7) << 3));
        *(uint2*)&QHu[off] = make_uint2(h0, h1);
        *(uint2*)&QLu[off] = make_uint2(l0, l1);
    }

    float acc[16][4];
#pragma unroll
    for (int nt = 0; nt < 16; nt++)
#pragma unroll
        for (int j = 0; j < 4; j++) acc[nt][j] = 0.0f;

    float mA = -1e30f, mB = -1e30f, lA = 0.0f, lB = 0.0f;
    const int rA   = 16 * w + g;        // rA & 7 == g
    const int rowA = qb + rA;
    const int rowB = rowA + 8;

    const unsigned* qhA = &QHu[rA * 64];
    const unsigned* qhB = qhA + 8 * 64;
    const unsigned* qlA = &QLu[rA * 64];
    const unsigned* qlB = qlA + 8 * 64;

    unsigned* KH = KVu;                 // [32][64]
    unsigned* KL = KVu + 2048;
    unsigned* VH = KVu;                 // [16][128]
    unsigned* VL = KVu + 2048;

    for (int kt = ks0; kt < ks1; kt++) {
        const int kb = kt * KT;

        __syncthreads();   // prior AV reads / Q split done
        // --- load + split K tile into KH/KL ---
#pragma unroll
        for (int i = 0; i < 8; i++) {
            int f4 = tid + 128 * i;        // 0..1023
            int row = f4 >> 5, c4 = f4 & 31;
            float4 v = *(const float4*)&g_k[(base + kb + row) * H_ + c4 * 4];
            unsigned h0, l0, h1, l1;
            split_h2(make_float2(v.x, v.y), h0, l0);
            split_h2(make_float2(v.z, v.w), h1, l1);
            int off = row * 64 + ((2 * c4) ^ ((row & 7) << 3));
            *(uint2*)&KH[off] = make_uint2(h0, h1);
            *(uint2*)&KL[off] = make_uint2(l0, l1);
        }
        __syncthreads();

        // --- QK^T: S[16 x 32] per warp, 4 n-tiles, 8 k16-chunks ---
        float s[4][4];
#pragma unroll
        for (int nt = 0; nt < 4; nt++)
#pragma unroll
            for (int j = 0; j < 4; j++) s[nt][j] = 0.0f;

#pragma unroll
        for (int ch = 0; ch < 8; ch++) {
            const int wq = 8 * (ch ^ g) + tig;   // pair (8ch+tig) ^ 8g
            unsigned aH[4], aL[4];
            aH[0] = qhA[wq];     aL[0] = qlA[wq];
            aH[1] = qhB[wq];     aL[1] = qlB[wq];
            aH[2] = qhA[wq + 4]; aL[2] = qlA[wq + 4];
            aH[3] = qhB[wq + 4]; aL[3] = qlB[wq + 4];
#pragma unroll
            for (int nt = 0; nt < 4; nt++) {
                const unsigned* kh = &KH[(8 * nt + g) * 64];
                const unsigned* kl = &KL[(8 * nt + g) * 64];
                unsigned bH[2], bL[2];
                bH[0] = kh[wq];     bL[0] = kl[wq];
                bH[1] = kh[wq + 4]; bL[1] = kl[wq + 4];
                MMA_F16(s[nt], aH, bH);
                MMA_F16(s[nt], aH, bL);
                MMA_F16(s[nt], aL, bH);
            }
        }

        // --- causal mask (sqrt(H) pre-folded into q) ---
#pragma unroll
        for (int nt = 0; nt < 4; nt++) {
            int c0 = kb + 8 * nt + 2 * tig;
            int c1 = c0 + 1;
            if (c0 > rowA) s[nt][0] = -1e30f;
            if (c1 > rowA) s[nt][1] = -1e30f;
            if (c0 > rowB) s[nt][2] = -1e30f;
            if (c1 > rowB) s[nt][3] = -1e30f;
        }

        // --- online softmax (quad reductions) ---
        float mxA = -1e30f, mxB = -1e30f;
#pragma unroll
        for (int nt = 0; nt < 4; nt++) {
            mxA = fmaxf(mxA, fmaxf(s[nt][0], s[nt][1]));
            mxB = fmaxf(mxB, fmaxf(s[nt][2], s[nt][3]));
        }
        mxA = fmaxf(mxA, __shfl_xor_sync(0xffffffffu, mxA, 1));
        mxA = fmaxf(mxA, __shfl_xor_sync(0xffffffffu, mxA, 2));
        mxB = fmaxf(mxB, __shfl_xor_sync(0xffffffffu, mxB, 1));
        mxB = fmaxf(mxB, __shfl_xor_sync(0xffffffffu, mxB, 2));

        float mAn = fmaxf(mA, mxA), mBn = fmaxf(mB, mxB);
        float cA = __expf(mA - mAn), cB = __expf(mB - mBn);
        float sumA = 0.0f, sumB = 0.0f;
#pragma unroll
        for (int nt = 0; nt < 4; nt++) {
            s[nt][0] = __expf(s[nt][0] - mAn);
            s[nt][1] = __expf(s[nt][1] - mAn);
            s[nt][2] = __expf(s[nt][2] - mBn);
            s[nt][3] = __expf(s[nt][3] - mBn);
            sumA += s[nt][0] + s[nt][1];
            sumB += s[nt][2] + s[nt][3];
        }
        sumA += __shfl_xor_sync(0xffffffffu, sumA, 1);
        sumA += __shfl_xor_sync(0xffffffffu, sumA, 2);
        sumB += __shfl_xor_sync(0xffffffffu, sumB, 1);
        sumB += __shfl_xor_sync(0xffffffffu, sumB, 2);
        lA = lA * cA + sumA;
        lB = lB * cB + sumB;
        mA = mAn; mB = mBn;
#pragma unroll
        for (int nt = 0; nt < 16; nt++) {
            acc[nt][0] *= cA; acc[nt][1] *= cA;
            acc[nt][2] *= cB; acc[nt][3] *= cB;
        }

        __syncthreads();   // QK reads of KH/KL done
        // --- load + split V tile into VH/VL (row-pair packed) ---
#pragma unroll
        for (int i = 0; i < 4; i++) {
            int cell = tid + 128 * i;      // 0..511
            int kp = cell >> 5, cg = cell & 31;
            float4 v0 = *(const float4*)&g_v[(base + kb + 2 * kp)     * H_ + cg * 4];
            float4 v1 = *(const float4*)&g_v[(base + kb + 2 * kp + 1) * H_ + cg * 4];
            unsigned h[4], l[4];
            split_h2(make_float2(v0.x, v1.x), h[0], l[0]);
            split_h2(make_float2(v0.y, v1.y), h[1], l[1]);
            split_h2(make_float2(v0.z, v1.z), h[2], l[2]);
            split_h2(make_float2(v0.w, v1.w), h[3], l[3]);
            int off = kp * 128 + ((cg ^ (2 * (kp & 3))) << 2);
            *(uint4*)&VH[off] = make_uint4(h[0], h[1], h[2], h[3]);
            *(uint4*)&VL[off] = make_uint4(l[0], l[1], l[2], l[3]);
        }
        __syncthreads();

        // --- AV: O[16 x 128] += P[16 x 32] * V[32 x 128], 2 k16-chunks ---
#pragma unroll
        for (int ch = 0; ch < 2; ch++) {
            unsigned aH[4], aL[4];
            split_h2(make_float2(s[2*ch][0],   s[2*ch][1]),   aH[0], aL[0]);
            split_h2(make_float2(s[2*ch][2],   s[2*ch][3]),   aH[1], aL[1]);
            split_h2(make_float2(s[2*ch+1][0], s[2*ch+1][1]), aH[2], aL[2]);
            split_h2(make_float2(s[2*ch+1][2], s[2*ch+1][3]), aH[3], aL[3]);

            const unsigned* vh0 = &VH[(8 * ch + tig) * 128 + g];
            const unsigned* vl0 = &VL[(8 * ch + tig) * 128 + g];
            const unsigned* vh4 = vh0 + 4 * 128;
            const unsigned* vl4 = vl0 + 4 * 128;
#pragma unroll
            for (int j = 0; j < 16; j++) {
                const int wv = 8 * (j ^ tig);   // (8j+g)^(8tig) - g
                unsigned bH[2], bL[2];
                bH[0] = vh0[wv]; bL[0] = vl0[wv];
                bH[1] = vh4[wv]; bL[1] = vl4[wv];
                MMA_F16(acc[j], aH, bH);
                MMA_F16(acc[j], aH, bL);
                MMA_F16(acc[j], aL, bH);
            }
        }
    }

    // --- epilogue: store partials (unnormalized o, m, l) ---
    const size_t growA = (size_t)split * M_ + base + rowA;
    const size_t growB = growA + 8;
#pragma unroll
    for (int nt = 0; nt < 16; nt++) {
        *(float2*)&g_opart[growA * H_ + 8 * nt + 2 * tig] =
            make_float2(acc[nt][0], acc[nt][1]);
        *(float2*)&g_opart[growB * H_ + 8 * nt + 2 * tig] =
            make_float2(acc[nt][2], acc[nt][3]);
    }
    if (tig == 0) {
        g_mpart[growA] = mA; g_lpart[growA] = lA;
        g_mpart[growB] = mB; g_lpart[growB] = lB;
    }
}

// ---------------------------------------------------------------------------
// Combine kernel: merge NSPLIT partials per row.
// ---------------------------------------------------------------------------
__global__ __launch_bounds__(256) void combine_kernel(float* __restrict__ out)
{
    const int t   = blockIdx.x * 256 + threadIdx.x;
    const int row = t >> 5;
    const int h   = (t & 31) * 4;

    const int qt  = (row & (S_ - 1)) >> 6;            // QTB=64
    const int nkt = 2 * (qt + 1);
    const int ck  = (nkt + NSPLIT - 1) / NSPLIT;

    float ms[NSPLIT];
    float M = -1e30f;
#pragma unroll
    for (int sp = 0; sp < NSPLIT; sp++) {
        bool valid = (sp * ck < nkt);
        ms[sp] = valid ? g_mpart[sp * M_ + row] : -1e30f;
        M = fmaxf(M, ms[sp]);
    }

    float L = 0.0f;
    float4 o = make_float4(0.f, 0.f, 0.f, 0.f);
#pragma unroll
    for (int sp = 0; sp < NSPLIT; sp++) {
        if (sp * ck < nkt) {
            float e = __expf(ms[sp] - M);
            L += e * g_lpart[sp * M_ + row];
            float4 v = *(const float4*)&g_opart[((size_t)sp * M_ + row) * H_ + h];
            o.x += e * v.x; o.y += e * v.y; o.z += e * v.z; o.w += e * v.w;
        }
    }
    float inv = 1.0f / L;
    float4 rr = make_float4(o.x * inv, o.y * inv, o.z * inv, o.w * inv);
    *(float4*)&out[(size_t)row * H_ + h] = rr;
}

// ---------------------------------------------------------------------------
extern "C" void kernel_launch(void* const* d_in, const int* in_sizes, int n_in,
                              void* d_out, int out_size)
{
    const float* x  = (const float*)d_in[0];
    const float* Wq = (const float*)d_in[1];
    const float* Wk = (const float*)d_in[2];
    const float* Wv = (const float*)d_in[3];
    float* out = (float*)d_out;

    dim3 pg(M_ / 64, 3);
    proj_kernel<<<pg, 128>>>(x, Wq, Wk, Wv);
    attn_kernel<<<NSPLIT * B_ * NQT, 128>>>();
    combine_kernel<<<(M_ * H_ / 4) / 256, 256>>>(out);
}

// round 14
// speedup vs baseline: 1.9762x; 1.3624x over previous
#include <cuda_runtime.h>
#include <cuda_fp16.h>
#include <cstdint>

#define B_ 4
#define S_ 2048
#define E_ 1024
#define H_ 128
#define M_ (B_*S_)

#define SCALE_ 11.31370849898476f   // sqrt(128)

#define NSPLIT 4
#define KT 32
#define QTB 64           // q rows per block
#define NQT (S_/QTB)     // 32 q-tiles per batch

// Scratch (device globals: no allocation allowed)
__device__ float g_q[M_*H_];
__device__ float g_k[M_*H_];
__device__ float g_v[M_*H_];
__device__ float g_opart[(size_t)NSPLIT*M_*H_];
__device__ float g_mpart[NSPLIT*M_];
__device__ float g_lpart[NSPLIT*M_];

// ---------------------------------------------------------------------------
// fp16 split helpers
// ---------------------------------------------------------------------------
__device__ __forceinline__ void split_h2(float2 v, unsigned& hi, unsigned& lo) {
    __half2 h = __floats2half2_rn(v.x, v.y);       // low half = v.x
    float2 hf = __half22float2(h);
    __half2 l = __floats2half2_rn(v.x - hf.x, v.y - hf.y);
    hi = *reinterpret_cast<unsigned*>(&h);
    lo = *reinterpret_cast<unsigned*>(&l);
}

#define MMA_F16(d, a, b) \
    asm volatile("mma.sync.aligned.m16n8k16.row.col.f32.f16.f16.f32 " \
        "{%0,%1,%2,%3}, {%4,%5,%6,%7}, {%8,%9}, {%0,%1,%2,%3};" \
        : "+f"((d)[0]), "+f"((d)[1]), "+f"((d)[2]), "+f"((d)[3]) \
        : "r"((a)[0]), "r"((a)[1]), "r"((a)[2]), "r"((a)[3]), \
          "r"((b)[0]), "r"((b)[1]))

// ---------------------------------------------------------------------------
// Projection GEMM via fp16x3 split mma.m16n8k16:
// out[m][h] = sum_e x[m][e]*W[h][e].  BM=64, BN=128(=H), BK=16.
// 128 threads = 4 warps (2m x 2n), warp tile 32x64, grid (128,3)=384.
// Loader splits f32 -> fp16x2 hi/lo planes once per tile:
//   XH/XL[64 rows][8 pairs], WH/WL[128 rows][8 pairs]; 12KB static smem.
// Swizzle: pair p of row r at p ^ (r&6) (bit0 kept -> uint2 stores aligned).
// Mainloop: 48 LDS.32 + 48 mma per warp per tile, zero cvt.
// ---------------------------------------------------------------------------
__global__ __launch_bounds__(128, 4) void proj_kernel(
    const float* __restrict__ x,
    const float* __restrict__ Wq,
    const float* __restrict__ Wk,
    const float* __restrict__ Wv)
{
    const float* W;
    float* out;
    float oscale;
    if (blockIdx.y == 0)      { W = Wq; out = g_q; oscale = SCALE_; }
    else if (blockIdx.y == 1) { W = Wk; out = g_k; oscale = 1.0f; }
    else                      { W = Wv; out = g_v; oscale = 1.0f; }

    __shared__ unsigned XH[64 * 8],  XL[64 * 8];    // 2KB each
    __shared__ unsigned WH[128 * 8], WL[128 * 8];   // 4KB each

    const int tid  = threadIdx.x;
    const int w    = tid >> 5;
    const int lane = tid & 31;
    const int g    = lane >> 2;
    const int tig  = lane & 3;

    const int m0 = blockIdx.x * 64;
    const int mw = (w >> 1) * 32;    // warp m-base (0 or 32)
    const int nw = (w & 1) * 64;     // warp n-base (0 or 64)

    // loader slots: X 2 f4/thread (rows 0..63), W 4 f4/thread (rows 0..127)
    int xoff[2], woff[4];
    const float* xsrc[2];
    const float* wsrc[4];
#pragma unroll
    for (int i = 0; i < 2; i++) {
        int f4 = tid + 128 * i;          // 0..255
        int row = f4 >> 2, c4 = f4 & 3;
        xoff[i] = row * 8 + ((2 * c4) ^ (row & 6));
        xsrc[i] = &x[(size_t)(m0 + row) * E_ + c4 * 4];
    }
#pragma unroll
    for (int i = 0; i < 4; i++) {
        int f4 = tid + 128 * i;          // 0..511
        int row = f4 >> 2, c4 = f4 & 3;
        woff[i] = row * 8 + ((2 * c4) ^ (row & 6));
        wsrc[i] = &W[(size_t)row * E_ + c4 * 4];
    }

    float acc[2][8][4];
#pragma unroll
    for (int i = 0; i < 2; i++)
#pragma unroll
        for (int j = 0; j < 8; j++)
#pragma unroll
            for (int c = 0; c < 4; c++) acc[i][j][c] = 0.0f;

    // fragment read constants
    const int p0 = tig ^ (g & 6);
    const int p1 = (tig + 4) ^ (g & 6);
    const unsigned* xhA = &XH[(mw + g) * 8];
    const unsigned* xlA = &XL[(mw + g) * 8];
    const unsigned* whB = &WH[(nw + g) * 8];
    const unsigned* wlB = &WL[(nw + g) * 8];

    for (int t = 0; t < E_ / 16; t++) {
        const int ko = t * 16;

        __syncthreads();   // prior compute reads done
        // --- load + split tile ---
#pragma unroll
        for (int i = 0; i < 2; i++) {
            float4 v = *(const float4*)(xsrc[i] + ko);
            unsigned h0, l0, h1, l1;
            split_h2(make_float2(v.x, v.y), h0, l0);
            split_h2(make_float2(v.z, v.w), h1, l1);
            *(uint2*)&XH[xoff[i]] = make_uint2(h0, h1);
            *(uint2*)&XL[xoff[i]] = make_uint2(l0, l1);
        }
#pragma unroll
        for (int i = 0; i < 4; i++) {
            float4 v = *(const float4*)(wsrc[i] + ko);
            unsigned h0, l0, h1, l1;
            split_h2(make_float2(v.x, v.y), h0, l0);
            split_h2(make_float2(v.z, v.w), h1, l1);
            *(uint2*)&WH[woff[i]] = make_uint2(h0, h1);
            *(uint2*)&WL[woff[i]] = make_uint2(l0, l1);
        }
        __syncthreads();

        // --- compute: 1 k16-chunk, 2m x 8n x 3 = 48 mma ---
        unsigned aH[2][4], aL[2][4];
#pragma unroll
        for (int i = 0; i < 2; i++) {
            const unsigned* xh = xhA + 16 * 8 * i;   // rows mw+16i+g
            const unsigned* xl = xlA + 16 * 8 * i;
            aH[i][0] = xh[p0]; aH[i][1] = xh[64 + p0];   // +8 rows = +64 words
            aH[i][2] = xh[p1]; aH[i][3] = xh[64 + p1];
            aL[i][0] = xl[p0]; aL[i][1] = xl[64 + p0];
            aL[i][2] = xl[p1]; aL[i][3] = xl[64 + p1];
        }
#pragma unroll
        for (int j = 0; j < 8; j++) {
            const unsigned* wh = whB + 8 * 8 * j;    // rows nw+8j+g
            const unsigned* wl = wlB + 8 * 8 * j;
            unsigned bH[2], bL[2];
            bH[0] = wh[p0]; bH[1] = wh[p1];
            bL[0] = wl[p0]; bL[1] = wl[p1];
#pragma unroll
            for (int i = 0; i < 2; i++) {
                MMA_F16(acc[i][j], aH[i], bH);
                MMA_F16(acc[i][j], aH[i], bL);
                MMA_F16(acc[i][j], aL[i], bH);
            }
        }
    }

    // --- epilogue: C rows m0+mw+16i+{g, g+8}, cols nw+8j+2tig(+1) ---
#pragma unroll
    for (int i = 0; i < 2; i++) {
        const size_t r0 = (size_t)(m0 + mw + 16 * i + g);
#pragma unroll
        for (int j = 0; j < 8; j++) {
            const int col = nw + 8 * j + 2 * tig;
            *(float2*)&out[r0 * H_ + col] =
                make_float2(acc[i][j][0] * oscale, acc[i][j][1] * oscale);
            *(float2*)&out[(r0 + 8) * H_ + col] =
                make_float2(acc[i][j][2] * oscale, acc[i][j][3] * oscale);
        }
    }
}

// ---------------------------------------------------------------------------
// Flash attention: fp16x3 split mma.m16n8k16 (R13 verified build, ~70us).
// ---------------------------------------------------------------------------
__global__ __launch_bounds__(128, 4) void attn_kernel()
{
    __shared__ unsigned QHu[QTB * 64];   // 16KB
    __shared__ unsigned QLu[QTB * 64];   // 16KB
    __shared__ unsigned KVu[KT * 128];   // 16KB: K phase KH|KL, V phase VH|VL

    const int tid  = threadIdx.x;
    const int w    = tid >> 5;
    const int lane = tid & 31;
    const int g    = lane >> 2;
    const int tig  = lane & 3;

    const int bx   = blockIdx.x;
    const int wave = bx / 148;
    const int pos  = bx - wave * 148;
    int r;
    if      (wave == 1) r = 295 - pos;
    else if (wave == 3) r = 511 - pos;
    else                r = bx;

    const int qt    = (NQT - 1) - (r >> 4);
    const int sub   = r & 15;
    const int b     = sub & 3;
    const int split = sub >> 2;

    const int nkt = 2 * (qt + 1);
    const int ck  = (nkt + NSPLIT - 1) / NSPLIT;
    const int ks0 = split * ck;
    const int ks1 = min(ks0 + ck, nkt);
    if (ks0 >= ks1) return;

    const int    qb   = qt * QTB;
    const size_t base = (size_t)b * S_;

    // --- load + split Q once per block (pre-scaled by sqrt(H)) ---
#pragma unroll
    for (int i = 0; i < 16; i++) {
        int f4 = tid + 128 * i;            // 0..2047
        int row = f4 >> 5, c4 = f4 & 31;
        float4 v = *(const float4*)&g_q[(base + qb + row) * H_ + c4 * 4];
        unsigned h0, l0, h1, l1;
        split_h2(make_float2(v.x, v.y), h0, l0);
        split_h2(make_float2(v.z, v.w), h1, l1);
        int off = row * 64 + ((2 * c4) ^ ((row & 7) << 3));
        *(uint2*)&QHu[off] = make_uint2(h0, h1);
        *(uint2*)&QLu[off] = make_uint2(l0, l1);
    }

    float acc[16][4];
#pragma unroll
    for (int nt = 0; nt < 16; nt++)
#pragma unroll
        for (int j = 0; j < 4; j++) acc[nt][j] = 0.0f;

    float mA = -1e30f, mB = -1e30f, lA = 0.0f, lB = 0.0f;
    const int rA   = 16 * w + g;        // rA & 7 == g
    const int rowA = qb + rA;
    const int rowB = rowA + 8;

    const unsigned* qhA = &QHu[rA * 64];
    const unsigned* qhB = qhA + 8 * 64;
    const unsigned* qlA = &QLu[rA * 64];
    const unsigned* qlB = qlA + 8 * 64;

    unsigned* KH = KVu;                 // [32][64]
    unsigned* KL = KVu + 2048;
    unsigned* VH = KVu;                 // [16][128]
    unsigned* VL = KVu + 2048;

    for (int kt = ks0; kt < ks1; kt++) {
        const int kb = kt * KT;

        __syncthreads();   // prior AV reads / Q split done
        // --- load + split K tile into KH/KL ---
#pragma unroll
        for (int i = 0; i < 8; i++) {
            int f4 = tid + 128 * i;        // 0..1023
            int row = f4 >> 5, c4 = f4 & 31;
            float4 v = *(const float4*)&g_k[(base + kb + row) * H_ + c4 * 4];
            unsigned h0, l0, h1, l1;
            split_h2(make_float2(v.x, v.y), h0, l0);
            split_h2(make_float2(v.z, v.w), h1, l1);
            int off = row * 64 + ((2 * c4) ^ ((row & 7) << 3));
            *(uint2*)&KH[off] = make_uint2(h0, h1);
            *(uint2*)&KL[off] = make_uint2(l0, l1);
        }
        __syncthreads();

        // --- QK^T: S[16 x 32] per warp, 4 n-tiles, 8 k16-chunks ---
        float s[4][4];
#pragma unroll
        for (int nt = 0; nt < 4; nt++)
#pragma unroll
            for (int j = 0; j < 4; j++) s[nt][j] = 0.0f;

#pragma unroll
        for (int ch = 0; ch < 8; ch++) {
            const int wq = 8 * (ch ^ g) + tig;
            unsigned aH[4], aL[4];
            aH[0] = qhA[wq];     aL[0] = qlA[wq];
            aH[1] = qhB[wq];     aL[1] = qlB[wq];
            aH[2] = qhA[wq + 4]; aL[2] = qlA[wq + 4];
            aH[3] = qhB[wq + 4]; aL[3] = qlB[wq + 4];
#pragma unroll
            for (int nt = 0; nt < 4; nt++) {
                const unsigned* kh = &KH[(8 * nt + g) * 64];
                const unsigned* kl = &KL[(8 * nt + g) * 64];
                unsigned bH[2], bL[2];
                bH[0] = kh[wq];     bL[0] = kl[wq];
                bH[1] = kh[wq + 4]; bL[1] = kl[wq + 4];
                MMA_F16(s[nt], aH, bH);
                MMA_F16(s[nt], aH, bL);
                MMA_F16(s[nt], aL, bH);
            }
        }

        // --- causal mask ---
#pragma unroll
        for (int nt = 0; nt < 4; nt++) {
            int c0 = kb + 8 * nt + 2 * tig;
            int c1 = c0 + 1;
            if (c0 > rowA) s[nt][0] = -1e30f;
            if (c1 > rowA) s[nt][1] = -1e30f;
            if (c0 > rowB) s[nt][2] = -1e30f;
            if (c1 > rowB) s[nt][3] = -1e30f;
        }

        // --- online softmax ---
        float mxA = -1e30f, mxB = -1e30f;
#pragma unroll
        for (int nt = 0; nt < 4; nt++) {
            mxA = fmaxf(mxA, fmaxf(s[nt][0], s[nt][1]));
            mxB = fmaxf(mxB, fmaxf(s[nt][2], s[nt][3]));
        }
        mxA = fmaxf(mxA, __shfl_xor_sync(0xffffffffu, mxA, 1));
        mxA = fmaxf(mxA, __shfl_xor_sync(0xffffffffu, mxA, 2));
        mxB = fmaxf(mxB, __shfl_xor_sync(0xffffffffu, mxB, 1));
        mxB = fmaxf(mxB, __shfl_xor_sync(0xffffffffu, mxB, 2));

        float mAn = fmaxf(mA, mxA), mBn = fmaxf(mB, mxB);
        float cA = __expf(mA - mAn), cB = __expf(mB - mBn);
        float sumA = 0.0f, sumB = 0.0f;
#pragma unroll
        for (int nt = 0; nt < 4; nt++) {
            s[nt][0] = __expf(s[nt][0] - mAn);
            s[nt][1] = __expf(s[nt][1] - mAn);
            s[nt][2] = __expf(s[nt][2] - mBn);
            s[nt][3] = __expf(s[nt][3] - mBn);
            sumA += s[nt][0] + s[nt][1];
            sumB += s[nt][2] + s[nt][3];
        }
        sumA += __shfl_xor_sync(0xffffffffu, sumA, 1);
        sumA += __shfl_xor_sync(0xffffffffu, sumA, 2);
        sumB += __shfl_xor_sync(0xffffffffu, sumB, 1);
        sumB += __shfl_xor_sync(0xffffffffu, sumB, 2);
        lA = lA * cA + sumA;
        lB = lB * cB + sumB;
        mA = mAn; mB = mBn;
#pragma unroll
        for (int nt = 0; nt < 16; nt++) {
            acc[nt][0] *= cA; acc[nt][1] *= cA;
            acc[nt][2] *= cB; acc[nt][3] *= cB;
        }

        __syncthreads();   // QK reads of KH/KL done
        // --- load + split V tile into VH/VL (row-pair packed) ---
#pragma unroll
        for (int i = 0; i < 4; i++) {
            int cell = tid + 128 * i;      // 0..511
            int kp = cell >> 5, cg = cell & 31;
            float4 v0 = *(const float4*)&g_v[(base + kb + 2 * kp)     * H_ + cg * 4];
            float4 v1 = *(const float4*)&g_v[(base + kb + 2 * kp + 1) * H_ + cg * 4];
            unsigned h[4], l[4];
            split_h2(make_float2(v0.x, v1.x), h[0], l[0]);
            split_h2(make_float2(v0.y, v1.y), h[1], l[1]);
            split_h2(make_float2(v0.z, v1.z), h[2], l[2]);
            split_h2(make_float2(v0.w, v1.w), h[3], l[3]);
            int off = kp * 128 + ((cg ^ (2 * (kp & 3))) << 2);
            *(uint4*)&VH[off] = make_uint4(h[0], h[1], h[2], h[3]);
            *(uint4*)&VL[off] = make_uint4(l[0], l[1], l[2], l[3]);
        }
        __syncthreads();

        // --- AV: O[16 x 128] += P[16 x 32] * V[32 x 128], 2 k16-chunks ---
#pragma unroll
        for (int ch = 0; ch < 2; ch++) {
            unsigned aH[4], aL[4];
            split_h2(make_float2(s[2*ch][0],   s[2*ch][1]),   aH[0], aL[0]);
            split_h2(make_float2(s[2*ch][2],   s[2*ch][3]),   aH[1], aL[1]);
            split_h2(make_float2(s[2*ch+1][0], s[2*ch+1][1]), aH[2], aL[2]);
            split_h2(make_float2(s[2*ch+1][2], s[2*ch+1][3]), aH[3], aL[3]);

            const unsigned* vh0 = &VH[(8 * ch + tig) * 128 + g];
            const unsigned* vl0 = &VL[(8 * ch + tig) * 128 + g];
            const unsigned* vh4 = vh0 + 4 * 128;
            const unsigned* vl4 = vl0 + 4 * 128;
#pragma unroll
            for (int j = 0; j < 16; j++) {
                const int wv = 8 * (j ^ tig);
                unsigned bH[2], bL[2];
                bH[0] = vh0[wv]; bL[0] = vl0[wv];
                bH[1] = vh4[wv]; bL[1] = vl4[wv];
                MMA_F16(acc[j], aH, bH);
                MMA_F16(acc[j], aH, bL);
                MMA_F16(acc[j], aL, bH);
            }
        }
    }

    // --- epilogue: store partials (unnormalized o, m, l) ---
    const size_t growA = (size_t)split * M_ + base + rowA;
    const size_t growB = growA + 8;
#pragma unroll
    for (int nt = 0; nt < 16; nt++) {
        *(float2*)&g_opart[growA * H_ + 8 * nt + 2 * tig] =
            make_float2(acc[nt][0], acc[nt][1]);
        *(float2*)&g_opart[growB * H_ + 8 * nt + 2 * tig] =
            make_float2(acc[nt][2], acc[nt][3]);
    }
    if (tig == 0) {
        g_mpart[growA] = mA; g_lpart[growA] = lA;
        g_mpart[growB] = mB; g_lpart[growB] = lB;
    }
}

// ---------------------------------------------------------------------------
// Combine kernel: merge NSPLIT partials per row.
// ---------------------------------------------------------------------------
__global__ __launch_bounds__(256) void combine_kernel(float* __restrict__ out)
{
    const int t   = blockIdx.x * 256 + threadIdx.x;
    const int row = t >> 5;
    const int h   = (t & 31) * 4;

    const int qt  = (row & (S_ - 1)) >> 6;            // QTB=64
    const int nkt = 2 * (qt + 1);
    const int ck  = (nkt + NSPLIT - 1) / NSPLIT;

    float ms[NSPLIT];
    float M = -1e30f;
#pragma unroll
    for (int sp = 0; sp < NSPLIT; sp++) {
        bool valid = (sp * ck < nkt);
        ms[sp] = valid ? g_mpart[sp * M_ + row] : -1e30f;
        M = fmaxf(M, ms[sp]);
    }

    float L = 0.0f;
    float4 o = make_float4(0.f, 0.f, 0.f, 0.f);
#pragma unroll
    for (int sp = 0; sp < NSPLIT; sp++) {
        if (sp * ck < nkt) {
            float e = __expf(ms[sp] - M);
            L += e * g_lpart[sp * M_ + row];
            float4 v = *(const float4*)&g_opart[((size_t)sp * M_ + row) * H_ + h];
            o.x += e * v.x; o.y += e * v.y; o.z += e * v.z; o.w += e * v.w;
        }
    }
    float inv = 1.0f / L;
    float4 rr = make_float4(o.x * inv, o.y * inv, o.z * inv, o.w * inv);
    *(float4*)&out[(size_t)row * H_ + h] = rr;
}

// ---------------------------------------------------------------------------
extern "C" void kernel_launch(void* const* d_in, const int* in_sizes, int n_in,
                              void* d_out, int out_size)
{
    const float* x  = (const float*)d_in[0];
    const float* Wq = (const float*)d_in[1];
    const float* Wk = (const float*)d_in[2];
    const float* Wv = (const float*)d_in[3];
    float* out = (float*)d_out;

    dim3 pg(M_ / 64, 3);
    proj_kernel<<<pg, 128>>>(x, Wq, Wk, Wv);
    attn_kernel<<<NSPLIT * B_ * NQT, 128>>>();
    combine_kernel<<<(M_ * H_ / 4) / 256, 256>>>(out);
}